// round 12
// baseline (speedup 1.0000x reference)
#include <cuda_runtime.h>
#include <cuda_fp16.h>
#include <math_constants.h>
#include <cstdint>

// Problem constants
#define NROWS 16384
#define NA    256
#define NF    2048
#define NFTOT (NROWS * NF)
#define GAMMA 1.5f
#define BN_EPS 1e-5f

#define BKB   32            // K per pipeline stage
#define NKIT  (NA / BKB)    // 8
#define STG_BYTES 16384     // A 8KB + B 8KB
#define NSTAGE 4            // 64KB smem -> 2 CTAs/SM (16 warps/SM)
#define GEMM_CTAS ((NF / 128) * (NROWS / 128))   // 2048

// ---------------- scratch (allocation-free: __device__ globals) ----------------
__device__ __half g_Xh[NROWS * NF];              // GEMM output (fp16)
__device__ __half g_Ah[(size_t)NROWS * NA];      // fp16(a)
__device__ __half g_Wh[(size_t)NF * NA];         // fp16(W)
__device__ float  g_colsum[NF];
__device__ float  g_colsq[NF];
__device__ float  g_scale[NF];
__device__ float  g_shift[NF];
__device__ unsigned int g_done = 0;              // last-CTA counter (self-resetting)

// ================= PTX helpers (baseline ISA only: valid on sm_103) =================
__device__ __forceinline__ uint32_t smem_u32(const void* p) {
    uint32_t a;
    asm("{ .reg .u64 t; cvta.to.shared.u64 t, %1; cvt.u32.u64 %0, t; }" : "=r"(a) : "l"(p));
    return a;
}
__device__ __forceinline__ void cp16(uint32_t sm, const void* g) {
    asm volatile("cp.async.cg.shared.global [%0], [%1], 16;" :: "r"(sm),
                 "l"(__cvta_generic_to_global(g)));
}
#define CP_COMMIT() asm volatile("cp.async.commit_group;" ::: "memory")
#define CP_WAIT(n)  asm volatile("cp.async.wait_group %0;" :: "n"(n) : "memory")

__device__ __forceinline__ void ldsm_x4(uint32_t& r0, uint32_t& r1, uint32_t& r2,
                                        uint32_t& r3, uint32_t addr) {
    asm volatile("ldmatrix.sync.aligned.m8n8.x4.shared.b16 {%0,%1,%2,%3}, [%4];"
        : "=r"(r0), "=r"(r1), "=r"(r2), "=r"(r3) : "r"(addr));
}
__device__ __forceinline__ void mma16816(float* d, const uint32_t* a,
                                         uint32_t b0, uint32_t b1) {
    asm volatile("mma.sync.aligned.m16n8k16.row.col.f32.f16.f16.f32 "
        "{%0,%1,%2,%3}, {%4,%5,%6,%7}, {%8,%9}, {%0,%1,%2,%3};"
        : "+f"(d[0]), "+f"(d[1]), "+f"(d[2]), "+f"(d[3])
        : "r"(a[0]), "r"(a[1]), "r"(a[2]), "r"(a[3]), "r"(b0), "r"(b1));
}
__device__ __forceinline__ uint32_t h2_bits(__half2 h) {
    union { __half2 h; uint32_t u; } cv;
    cv.h = h;
    return cv.u;
}
__device__ __forceinline__ float2 h2_f2(uint32_t u) {
    union { uint32_t u; __half2 h; } cv; cv.u = u;
    return __half22float2(cv.h);
}

// ================================================================
// K1: merged fp32->fp16 convert of A and W + zero stats.
// ================================================================
#define CONV_A_BLOCKS (NROWS * NA / 1024)   // 4096
#define CONV_W_BLOCKS (NF * NA / 1024)      // 512
__global__ void __launch_bounds__(256)
conv_kernel(const float* __restrict__ a, const float* __restrict__ W) {
    if (blockIdx.x < CONV_A_BLOCKS) {
        int i4 = blockIdx.x * 256 + threadIdx.x;
        float4 v = ((const float4*)a)[i4];
        uint2 o;
        o.x = h2_bits(__floats2half2_rn(v.x, v.y));
        o.y = h2_bits(__floats2half2_rn(v.z, v.w));
        ((uint2*)g_Ah)[i4] = o;
    } else {
        int b = blockIdx.x - CONV_A_BLOCKS;
        int i4 = b * 256 + threadIdx.x;
        float4 v = ((const float4*)W)[i4];
        uint2 o;
        o.x = h2_bits(__floats2half2_rn(v.x, v.y));
        o.y = h2_bits(__floats2half2_rn(v.z, v.w));
        ((uint2*)g_Wh)[i4] = o;
        if (b < 8) {
            int f = b * 256 + threadIdx.x;
            g_colsum[f] = 0.0f; g_colsq[f] = 0.0f;
        }
    }
}

// ================================================================
// K2: HMMA GEMM fp16->fp32. R4 geometry at K=256: CTA 128x128,
// 8 warps (4M x 2N), warp tile 32x64, BK=32, 4-stage cp.async ring
// (lookahead 3). 16 warps/SM -> effective MMA rt ~13.7 (vs 16 at
// 8 warps/SM). smem row = 32 halves = 64B = 4 segs;
// swizzle seg ^= (row>>1)&3. Epilogue: fp16 store + fused column
// stats + LAST-CTA BN finalize (scale/shift) — no separate kernel.
// ================================================================
__global__ void __launch_bounds__(256, 2)
gemm_hmma_kernel(const float* __restrict__ bn_w, const float* __restrict__ bn_b) {
    extern __shared__ char smem[];
    const uint32_t sb = smem_u32(smem);
    const int tid = threadIdx.x;
    const int wid = tid >> 5, lid = tid & 31;
    const int warpM = wid & 3, warpN = wid >> 2;
    const int m0 = blockIdx.y * 128;
    const int f0 = blockIdx.x * 128;

    // ---- hoisted cp.async addresses (per thread: 2 A rows + 2 B rows) ----
    const int seg = tid & 3;
    const int r0 = tid >> 2, r1 = r0 + 64;
    const uint32_t swA0 = (uint32_t)r0 * 64u + (uint32_t)((seg ^ ((r0 >> 1) & 3)) << 4);
    const uint32_t swA1 = (uint32_t)r1 * 64u + (uint32_t)((seg ^ ((r1 >> 1) & 3)) << 4);
    const uint32_t sA0 = sb + swA0,        sA1 = sb + swA1;
    const uint32_t sB0 = sb + 8192 + swA0, sB1 = sb + 8192 + swA1;
    const char* gA0 = (const char*)(g_Ah + (size_t)(m0 + r0) * NA) + seg * 16;
    const char* gA1 = (const char*)(g_Ah + (size_t)(m0 + r1) * NA) + seg * 16;
    const char* gB0 = (const char*)(g_Wh + (size_t)(f0 + r0) * NA) + seg * 16;
    const char* gB1 = (const char*)(g_Wh + (size_t)(f0 + r1) * NA) + seg * 16;

    // ---- hoisted ldmatrix addresses (12 per thread) ----
    uint32_t adA[2][2], adB[4][2];
#pragma unroll
    for (int ks = 0; ks < 2; ks++) {
        const int segb = (lid >> 4) + ks * 2;
#pragma unroll
        for (int t = 0; t < 2; t++) {
            int r = warpM * 32 + t * 16 + (lid & 15);
            adA[t][ks] = sb + (uint32_t)r * 64u
                       + (uint32_t)((segb ^ ((r >> 1) & 3)) << 4);
        }
#pragma unroll
        for (int u = 0; u < 4; u++) {
            int r = warpN * 64 + u * 16 + (lid & 15);
            adB[u][ks] = sb + 8192u + (uint32_t)r * 64u
                       + (uint32_t)((segb ^ ((r >> 1) & 3)) << 4);
        }
    }

    float acc[2][8][4];
#pragma unroll
    for (int t = 0; t < 2; t++)
#pragma unroll
        for (int j = 0; j < 8; j++)
#pragma unroll
            for (int e = 0; e < 4; e++) acc[t][j][e] = 0.0f;

    // prologue: 3 stages in flight (stage p holds iteration p)
#pragma unroll
    for (int p = 0; p < 3; p++) {
        const uint32_t so = p * STG_BYTES;
        cp16(sA0 + so, gA0 + p * 64); cp16(sB0 + so, gB0 + p * 64);
        cp16(sA1 + so, gA1 + p * 64); cp16(sB1 + so, gB1 + p * 64);
        CP_COMMIT();
    }

#pragma unroll 1
    for (int it4 = 0; it4 < NKIT; it4 += 4) {
#pragma unroll
        for (int ii = 0; ii < 4; ii++) {
            const int it = it4 + ii;
            CP_WAIT(2);
            __syncthreads();
            if (it + 3 < NKIT) {
                const uint32_t so = ((ii + 3) & 3) * STG_BYTES;
                const int off = (it + 3) * 64;
                cp16(sA0 + so, gA0 + off); cp16(sB0 + so, gB0 + off);
                cp16(sA1 + so, gA1 + off); cp16(sB1 + so, gB1 + off);
            }
            CP_COMMIT();

            const uint32_t so = ii * STG_BYTES;   // compile-time constant
#pragma unroll
            for (int ks = 0; ks < 2; ks++) {
                uint32_t af[2][4], bf[4][4];
#pragma unroll
                for (int t = 0; t < 2; t++)
                    ldsm_x4(af[t][0], af[t][1], af[t][2], af[t][3], adA[t][ks] + so);
#pragma unroll
                for (int u = 0; u < 4; u++)
                    ldsm_x4(bf[u][0], bf[u][1], bf[u][2], bf[u][3], adB[u][ks] + so);
#pragma unroll
                for (int t = 0; t < 2; t++)
#pragma unroll
                    for (int u = 0; u < 4; u++) {
                        mma16816(acc[t][2 * u],     af[t], bf[u][0], bf[u][2]);
                        mma16816(acc[t][2 * u + 1], af[t], bf[u][1], bf[u][3]);
                    }
            }
        }
    }

    // epilogue: C -> g_Xh (half2 stores) + fused column stats (fp32)
#pragma unroll
    for (int t = 0; t < 2; t++) {
        const int rbase = m0 + warpM * 32 + t * 16 + (lid >> 2);
#pragma unroll
        for (int j = 0; j < 8; j++) {
            const int col = f0 + warpN * 64 + j * 8 + (lid & 3) * 2;
            *(__half2*)&g_Xh[(size_t)rbase * NF + col] =
                __floats2half2_rn(acc[t][j][0], acc[t][j][1]);
            *(__half2*)&g_Xh[(size_t)(rbase + 8) * NF + col] =
                __floats2half2_rn(acc[t][j][2], acc[t][j][3]);
        }
    }
    const unsigned FULL = 0xffffffffu;
#pragma unroll
    for (int j = 0; j < 8; j++) {
        float s0 = acc[0][j][0] + acc[0][j][2] + acc[1][j][0] + acc[1][j][2];
        float s1 = acc[0][j][1] + acc[0][j][3] + acc[1][j][1] + acc[1][j][3];
        float q0 = acc[0][j][0]*acc[0][j][0] + acc[0][j][2]*acc[0][j][2]
                 + acc[1][j][0]*acc[1][j][0] + acc[1][j][2]*acc[1][j][2];
        float q1 = acc[0][j][1]*acc[0][j][1] + acc[0][j][3]*acc[0][j][3]
                 + acc[1][j][1]*acc[1][j][1] + acc[1][j][3]*acc[1][j][3];
#pragma unroll
        for (int o = 16; o >= 4; o >>= 1) {
            s0 += __shfl_down_sync(FULL, s0, o);
            s1 += __shfl_down_sync(FULL, s1, o);
            q0 += __shfl_down_sync(FULL, q0, o);
            q1 += __shfl_down_sync(FULL, q1, o);
        }
        if (lid < 4) {
            const int col = f0 + warpN * 64 + j * 8 + lid * 2;
            atomicAdd(&g_colsum[col], s0);
            atomicAdd(&g_colsum[col + 1], s1);
            atomicAdd(&g_colsq[col], q0);
            atomicAdd(&g_colsq[col + 1], q1);
        }
    }

    // ---- fused BN finalize: last CTA computes scale/shift ----
    __shared__ unsigned s_rank;
    __threadfence();                       // make our atomics visible
    __syncthreads();                       // all threads' atomics issued
    if (tid == 0) s_rank = atomicAdd(&g_done, 1u);
    __syncthreads();
    if (s_rank == GEMM_CTAS - 1) {
        if (tid == 0) g_done = 0;          // reset for graph replay
        __threadfence();                   // acquire other CTAs' stats
        const float inv_n = 1.0f / (float)NROWS;
#pragma unroll
        for (int f = tid; f < NF; f += 256) {
            float mean = g_colsum[f] * inv_n;
            float var  = fmaxf(g_colsq[f] * inv_n - mean * mean, 0.0f);
            float rstd = rsqrtf(var + BN_EPS);
            float sc = bn_w[f] * rstd;
            g_scale[f] = sc;
            g_shift[f] = bn_b[f] - mean * sc;
        }
    }
}

// ================================================================
// K4: per-row sparsemax + outputs (coalesced; lean)
// ================================================================
__device__ __forceinline__ float block_reduce(float v, float* buf, bool do_max) {
    const unsigned FULL = 0xffffffffu;
#pragma unroll
    for (int o = 16; o > 0; o >>= 1) {
        float t = __shfl_down_sync(FULL, v, o);
        v = do_max ? fmaxf(v, t) : (v + t);
    }
    const int w = threadIdx.x >> 5, l = threadIdx.x & 31;
    if (l == 0) buf[w] = v;
    __syncthreads();
    if (threadIdx.x < 8) {
        v = buf[threadIdx.x];
#pragma unroll
        for (int o = 4; o > 0; o >>= 1) {
            float t = __shfl_down_sync(0xffu, v, o);
            v = do_max ? fmaxf(v, t) : (v + t);
        }
        if (threadIdx.x == 0) buf[0] = v;
    }
    __syncthreads();
    float r = buf[0];
    __syncthreads();
    return r;
}

__global__ void __launch_bounds__(256)
row_kernel(const float* __restrict__ ps, float* __restrict__ out) {
    __shared__ float s_a[NF];
    __shared__ float s_b[NF];
    __shared__ float rbuf[8];

    const int row = blockIdx.x;
    const int tid = threadIdx.x;

    const uint2*  xp  = (const uint2*)(g_Xh + (size_t)row * NF);
    const float4* pp  = (const float4*)(ps  + (size_t)row * NF);
    const float4* scp = (const float4*)g_scale;
    const float4* shp = (const float4*)g_shift;

    float z[8], pv8[8];
    float S = 0.0f, mx = -CUDART_INF_F;

#pragma unroll
    for (int g = 0; g < 2; g++) {
        const int q = tid + g * 256;
        uint2  xv = xp[q];
        float4 pv = pp[q];
        float4 sc = scp[q], sh = shp[q];

        float2 x01 = h2_f2(xv.x);
        float2 x23 = h2_f2(xv.y);

        float z0 = fmaf(x01.x, sc.x, sh.x) * pv.x;
        float z1 = fmaf(x01.y, sc.y, sh.y) * pv.y;
        float z2 = fmaf(x23.x, sc.z, sh.z) * pv.z;
        float z3 = fmaf(x23.y, sc.w, sh.w) * pv.w;
        z[g*4+0]=z0; z[g*4+1]=z1; z[g*4+2]=z2; z[g*4+3]=z3;
        pv8[g*4+0]=pv.x; pv8[g*4+1]=pv.y; pv8[g*4+2]=pv.z; pv8[g*4+3]=pv.w;
        S += (z0 + z1) + (z2 + z3);
        mx = fmaxf(mx, fmaxf(fmaxf(z0, z1), fmaxf(z2, z3)));
    }

    S  = block_reduce(S,  rbuf, false);
    mx = block_reduce(mx, rbuf, true);

    float tau;
    if (1.0f + 2047.0f * mx - S > 0.0f) {
        tau = (S + 1.0f) * (1.0f / 2047.0f);
    } else {
        // exact fallback (ascending bitonic sort + scan) — effectively never taken
#pragma unroll
        for (int g = 0; g < 2; g++)
#pragma unroll
            for (int j = 0; j < 4; j++)
                s_a[(tid + g * 256) * 4 + j] = z[g * 4 + j];
        __syncthreads();
        for (int k = 2; k <= NF; k <<= 1)
            for (int j = k >> 1; j > 0; j >>= 1) {
                for (int i = tid; i < NF; i += 256) {
                    int ixj = i ^ j;
                    if (ixj > i) {
                        bool up = ((i & k) == 0);
                        float va = s_a[i], vb = s_a[ixj];
                        if ((va > vb) == up) { s_a[i] = vb; s_a[ixj] = va; }
                    }
                }
                __syncthreads();
            }
        float sv[8];
#pragma unroll
        for (int e = 0; e < 8; e++) sv[e] = s_a[tid + e * 256];
        float* src = s_a; float* dst = s_b;
        for (int off = 1; off < NF; off <<= 1) {
            for (int i = tid; i < NF; i += 256)
                dst[i] = src[i] + ((i >= off) ? src[i - off] : 0.0f);
            __syncthreads();
            float* t = src; src = dst; dst = t;
        }
        float kf = 0.0f;
#pragma unroll
        for (int e = 0; e < 8; e++) {
            int i = tid + e * 256;
            if (1.0f + (float)i * sv[e] - src[i] > 0.0f) kf = fmaxf(kf, (float)i);
        }
        kf = block_reduce(kf, rbuf, true);
        int k = (int)kf;
        tau = (src[k] + 1.0f) / (float)k;
        __syncthreads();
    }

    float* om = out + (size_t)row * NF;
    float* op = out + (size_t)NFTOT + (size_t)row * NF;
#pragma unroll
    for (int g = 0; g < 2; g++) {
        const int q = tid + g * 256;
        float m0 = fmaxf(z[g*4+0] - tau, 0.0f);
        float m1 = fmaxf(z[g*4+1] - tau, 0.0f);
        float m2 = fmaxf(z[g*4+2] - tau, 0.0f);
        float m3 = fmaxf(z[g*4+3] - tau, 0.0f);
        ((float4*)om)[q] = make_float4(m0, m1, m2, m3);
        ((float4*)op)[q] = make_float4(pv8[g*4+0] * (GAMMA - m0),
                                       pv8[g*4+1] * (GAMMA - m1),
                                       pv8[g*4+2] * (GAMMA - m2),
                                       pv8[g*4+3] * (GAMMA - m3));
    }
}

// ================================================================
// launch: a, ps, W, b, bn_w, bn_b -> out = concat(m, new_ps)
// ================================================================
extern "C" void kernel_launch(void* const* d_in, const int* in_sizes, int n_in,
                              void* d_out, int out_size) {
    const float* a    = (const float*)d_in[0];
    const float* ps   = (const float*)d_in[1];
    const float* W    = (const float*)d_in[2];
    const float* bn_w = (const float*)d_in[4];
    const float* bn_b = (const float*)d_in[5];
    float* out = (float*)d_out;

    cudaFuncSetAttribute(gemm_hmma_kernel,
                         cudaFuncAttributeMaxDynamicSharedMemorySize,
                         NSTAGE * STG_BYTES);

    conv_kernel<<<CONV_A_BLOCKS + CONV_W_BLOCKS, 256>>>(a, W);
    gemm_hmma_kernel<<<dim3(NF / 128, NROWS / 128), 256, NSTAGE * STG_BYTES>>>(bn_w, bn_b);
    row_kernel<<<NROWS, 256>>>(ps, out);
}

// round 13
// speedup vs baseline: 1.0541x; 1.0541x over previous
#include <cuda_runtime.h>
#include <cuda_fp16.h>
#include <math_constants.h>
#include <cstdint>

// Problem constants
#define NROWS 16384
#define NA    256
#define NF    2048
#define NFTOT (NROWS * NF)
#define GAMMA 1.5f
#define BN_EPS 1e-5f

#define BKB   64            // K per pipeline stage
#define NKIT  (NA / BKB)    // 4
#define STG_BYTES 32768     // A 16KB + B 16KB
#define NSTAGE 3            // 96KB smem -> 2 CTAs/SM
#define GEMM_CTAS ((NF / 128) * (NROWS / 128))   // 2048

// ---------------- scratch (allocation-free: __device__ globals) ----------------
__device__ __half g_Xh[NROWS * NF];              // GEMM output (fp16)
__device__ __half g_Ah[(size_t)NROWS * NA];      // fp16(a)
__device__ __half g_Wh[(size_t)NF * NA];         // fp16(W)
__device__ float  g_colsum[NF];
__device__ float  g_colsq[NF];
__device__ float  g_scale[NF];
__device__ float  g_shift[NF];
__device__ unsigned int g_done = 0;              // last-CTA counter (self-resetting)

// ================= PTX helpers (baseline ISA only: valid on sm_103) =================
__device__ __forceinline__ uint32_t smem_u32(const void* p) {
    uint32_t a;
    asm("{ .reg .u64 t; cvta.to.shared.u64 t, %1; cvt.u32.u64 %0, t; }" : "=r"(a) : "l"(p));
    return a;
}
__device__ __forceinline__ void cp16(uint32_t sm, const void* g) {
    asm volatile("cp.async.cg.shared.global [%0], [%1], 16;" :: "r"(sm),
                 "l"(__cvta_generic_to_global(g)));
}
#define CP_COMMIT() asm volatile("cp.async.commit_group;" ::: "memory")
#define CP_WAIT(n)  asm volatile("cp.async.wait_group %0;" :: "n"(n) : "memory")

__device__ __forceinline__ void ldsm_x4(uint32_t& r0, uint32_t& r1, uint32_t& r2,
                                        uint32_t& r3, uint32_t addr) {
    asm volatile("ldmatrix.sync.aligned.m8n8.x4.shared.b16 {%0,%1,%2,%3}, [%4];"
        : "=r"(r0), "=r"(r1), "=r"(r2), "=r"(r3) : "r"(addr));
}
__device__ __forceinline__ void mma16816(float* d, const uint32_t* a,
                                         uint32_t b0, uint32_t b1) {
    asm volatile("mma.sync.aligned.m16n8k16.row.col.f32.f16.f16.f32 "
        "{%0,%1,%2,%3}, {%4,%5,%6,%7}, {%8,%9}, {%0,%1,%2,%3};"
        : "+f"(d[0]), "+f"(d[1]), "+f"(d[2]), "+f"(d[3])
        : "r"(a[0]), "r"(a[1]), "r"(a[2]), "r"(a[3]), "r"(b0), "r"(b1));
}
__device__ __forceinline__ uint32_t h2_bits(__half2 h) {
    union { __half2 h; uint32_t u; } cv;
    cv.h = h;
    return cv.u;
}
__device__ __forceinline__ float2 h2_f2(uint32_t u) {
    union { uint32_t u; __half2 h; } cv; cv.u = u;
    return __half22float2(cv.h);
}

// ================================================================
// K1: merged fp32->fp16 convert of A and W + zero stats.
// 2 float4 per thread (fewer blocks; conv was launch-bound).
// blocks [0, 2048): A.  blocks [2048, 2304): W.
// (bias b omitted: cancelled exactly by BatchNorm mean subtraction)
// ================================================================
#define CONV_A_BLOCKS (NROWS * NA / 2048)   // 2048
#define CONV_W_BLOCKS (NF * NA / 2048)      // 256
__global__ void __launch_bounds__(256)
conv_kernel(const float* __restrict__ a, const float* __restrict__ W) {
    if (blockIdx.x < CONV_A_BLOCKS) {
        int i4 = blockIdx.x * 512 + threadIdx.x;
#pragma unroll
        for (int r = 0; r < 2; r++) {
            float4 v = ((const float4*)a)[i4 + r * 256];
            uint2 o;
            o.x = h2_bits(__floats2half2_rn(v.x, v.y));
            o.y = h2_bits(__floats2half2_rn(v.z, v.w));
            ((uint2*)g_Ah)[i4 + r * 256] = o;
        }
    } else {
        int b = blockIdx.x - CONV_A_BLOCKS;
        int i4 = b * 512 + threadIdx.x;
#pragma unroll
        for (int r = 0; r < 2; r++) {
            float4 v = ((const float4*)W)[i4 + r * 256];
            uint2 o;
            o.x = h2_bits(__floats2half2_rn(v.x, v.y));
            o.y = h2_bits(__floats2half2_rn(v.z, v.w));
            ((uint2*)g_Wh)[i4 + r * 256] = o;
        }
        if (b < 8) {
            int f = b * 256 + threadIdx.x;
            g_colsum[f] = 0.0f; g_colsq[f] = 0.0f;
        }
    }
}

// ================================================================
// K2: HMMA GEMM fp16->fp32 — exact R11 configuration (62us, at the
// mma.sync roofline): CTA 128x128, 4 warps (2M x 2N), warp tile
// 64x64, BK=64, 3-stage cp.async ring, lookahead 2.
// Epilogue: fp16 store + fused column stats + last-CTA BN finalize.
// ================================================================
__global__ void __launch_bounds__(128, 2)
gemm_hmma_kernel(const float* __restrict__ bn_w, const float* __restrict__ bn_b) {
    extern __shared__ char smem[];
    const uint32_t sb = smem_u32(smem);
    const int tid = threadIdx.x;
    const int wid = tid >> 5, lid = tid & 31;
    const int warpM = wid & 1, warpN = wid >> 1;
    const int m0 = blockIdx.y * 128;
    const int f0 = blockIdx.x * 128;

    const int s = tid & 7;
    const int r0 = tid >> 3;
    const uint32_t swc = (uint32_t)((s ^ (r0 & 7)) << 4);
    const uint32_t smA = sb + (uint32_t)r0 * 128u + swc;
    const uint32_t smB = smA + 16384u;
    const char* gA = (const char*)(g_Ah + (size_t)(m0 + r0) * NA) + s * 16;
    const char* gB = (const char*)(g_Wh + (size_t)(f0 + r0) * NA) + s * 16;

    uint32_t rbA[4], rbB[4], segoff[4];
#pragma unroll
    for (int t = 0; t < 4; t++) {
        rbA[t] = sb + (uint32_t)(warpM * 64 + t * 16 + (lid & 15)) * 128u;
        rbB[t] = sb + 16384u + (uint32_t)(warpN * 64 + t * 16 + (lid & 15)) * 128u;
    }
#pragma unroll
    for (int ks = 0; ks < 4; ks++)
        segoff[ks] = (uint32_t)(((2 * ks + (lid >> 4)) ^ (lid & 7)) << 4);

    float acc[4][8][4];
#pragma unroll
    for (int t = 0; t < 4; t++)
#pragma unroll
        for (int j = 0; j < 8; j++)
#pragma unroll
            for (int e = 0; e < 4; e++) acc[t][j][e] = 0.0f;

#pragma unroll
    for (int p = 0; p < 2; p++) {
        const uint32_t so = p * STG_BYTES;
        const int go = p * 128;
#pragma unroll
        for (int j = 0; j < 8; j++) {
            cp16(smA + so + j * 2048u, gA + (size_t)j * 16 * (NA * 2) + go);
            cp16(smB + so + j * 2048u, gB + (size_t)j * 16 * (NA * 2) + go);
        }
        CP_COMMIT();
    }

#pragma unroll
    for (int it = 0; it < NKIT; it++) {
        CP_WAIT(1);
        __syncthreads();
        if (it + 2 < NKIT) {
            const uint32_t so = ((it + 2) % 3) * STG_BYTES;
            const int go = (it + 2) * 128;
#pragma unroll
            for (int j = 0; j < 8; j++) {
                cp16(smA + so + j * 2048u, gA + (size_t)j * 16 * (NA * 2) + go);
                cp16(smB + so + j * 2048u, gB + (size_t)j * 16 * (NA * 2) + go);
            }
        }
        CP_COMMIT();

        const uint32_t so = (it % 3) * STG_BYTES;
#pragma unroll
        for (int ks = 0; ks < 4; ks++) {
            uint32_t af[4][4], bf[4][4];
#pragma unroll
            for (int t = 0; t < 4; t++)
                ldsm_x4(af[t][0], af[t][1], af[t][2], af[t][3],
                        rbA[t] + so + segoff[ks]);
#pragma unroll
            for (int u = 0; u < 4; u++)
                ldsm_x4(bf[u][0], bf[u][1], bf[u][2], bf[u][3],
                        rbB[u] + so + segoff[ks]);
#pragma unroll
            for (int t = 0; t < 4; t++)
#pragma unroll
                for (int u = 0; u < 4; u++) {
                    mma16816(acc[t][2 * u],     af[t], bf[u][0], bf[u][2]);
                    mma16816(acc[t][2 * u + 1], af[t], bf[u][1], bf[u][3]);
                }
        }
    }

    // epilogue: C -> g_Xh (half2 stores) + fused column stats (fp32)
#pragma unroll
    for (int t = 0; t < 4; t++) {
        const int rbase = m0 + warpM * 64 + t * 16 + (lid >> 2);
#pragma unroll
        for (int j = 0; j < 8; j++) {
            const int col = f0 + warpN * 64 + j * 8 + (lid & 3) * 2;
            *(__half2*)&g_Xh[(size_t)rbase * NF + col] =
                __floats2half2_rn(acc[t][j][0], acc[t][j][1]);
            *(__half2*)&g_Xh[(size_t)(rbase + 8) * NF + col] =
                __floats2half2_rn(acc[t][j][2], acc[t][j][3]);
        }
    }
    const unsigned FULL = 0xffffffffu;
#pragma unroll
    for (int j = 0; j < 8; j++) {
        float s0 = 0, s1 = 0, q0 = 0, q1 = 0;
#pragma unroll
        for (int t = 0; t < 4; t++) {
            s0 += acc[t][j][0] + acc[t][j][2];
            s1 += acc[t][j][1] + acc[t][j][3];
            q0 += acc[t][j][0]*acc[t][j][0] + acc[t][j][2]*acc[t][j][2];
            q1 += acc[t][j][1]*acc[t][j][1] + acc[t][j][3]*acc[t][j][3];
        }
#pragma unroll
        for (int o = 16; o >= 4; o >>= 1) {
            s0 += __shfl_down_sync(FULL, s0, o);
            s1 += __shfl_down_sync(FULL, s1, o);
            q0 += __shfl_down_sync(FULL, q0, o);
            q1 += __shfl_down_sync(FULL, q1, o);
        }
        if (lid < 4) {
            const int col = f0 + warpN * 64 + j * 8 + lid * 2;
            atomicAdd(&g_colsum[col], s0);
            atomicAdd(&g_colsum[col + 1], s1);
            atomicAdd(&g_colsq[col], q0);
            atomicAdd(&g_colsq[col + 1], q1);
        }
    }

    // ---- fused BN finalize: last CTA computes scale/shift ----
    __shared__ unsigned s_rank;
    __threadfence();                       // make our atomics visible
    __syncthreads();                       // all threads' atomics issued
    if (tid == 0) s_rank = atomicAdd(&g_done, 1u);
    __syncthreads();
    if (s_rank == GEMM_CTAS - 1) {
        if (tid == 0) g_done = 0;          // reset for graph replay
        __threadfence();                   // acquire other CTAs' stats
        const float inv_n = 1.0f / (float)NROWS;
#pragma unroll
        for (int f = tid; f < NF; f += 128) {
            float mean = g_colsum[f] * inv_n;
            float var  = fmaxf(g_colsq[f] * inv_n - mean * mean, 0.0f);
            float rstd = rsqrtf(var + BN_EPS);
            float sc = bn_w[f] * rstd;
            g_scale[f] = sc;
            g_shift[f] = bn_b[f] - mean * sc;
        }
    }
}

// ================================================================
// K4: per-row sparsemax + outputs (coalesced; lean)
// ================================================================
__device__ __forceinline__ float block_reduce(float v, float* buf, bool do_max) {
    const unsigned FULL = 0xffffffffu;
#pragma unroll
    for (int o = 16; o > 0; o >>= 1) {
        float t = __shfl_down_sync(FULL, v, o);
        v = do_max ? fmaxf(v, t) : (v + t);
    }
    const int w = threadIdx.x >> 5, l = threadIdx.x & 31;
    if (l == 0) buf[w] = v;
    __syncthreads();
    if (threadIdx.x < 8) {
        v = buf[threadIdx.x];
#pragma unroll
        for (int o = 4; o > 0; o >>= 1) {
            float t = __shfl_down_sync(0xffu, v, o);
            v = do_max ? fmaxf(v, t) : (v + t);
        }
        if (threadIdx.x == 0) buf[0] = v;
    }
    __syncthreads();
    float r = buf[0];
    __syncthreads();
    return r;
}

__global__ void __launch_bounds__(256)
row_kernel(const float* __restrict__ ps, float* __restrict__ out) {
    __shared__ float s_a[NF];
    __shared__ float s_b[NF];
    __shared__ float rbuf[8];

    const int row = blockIdx.x;
    const int tid = threadIdx.x;

    const uint2*  xp  = (const uint2*)(g_Xh + (size_t)row * NF);
    const float4* pp  = (const float4*)(ps  + (size_t)row * NF);
    const float4* scp = (const float4*)g_scale;
    const float4* shp = (const float4*)g_shift;

    float z[8], pv8[8];
    float S = 0.0f, mx = -CUDART_INF_F;

#pragma unroll
    for (int g = 0; g < 2; g++) {
        const int q = tid + g * 256;
        uint2  xv = xp[q];
        float4 pv = pp[q];
        float4 sc = scp[q], sh = shp[q];

        float2 x01 = h2_f2(xv.x);
        float2 x23 = h2_f2(xv.y);

        float z0 = fmaf(x01.x, sc.x, sh.x) * pv.x;
        float z1 = fmaf(x01.y, sc.y, sh.y) * pv.y;
        float z2 = fmaf(x23.x, sc.z, sh.z) * pv.z;
        float z3 = fmaf(x23.y, sc.w, sh.w) * pv.w;
        z[g*4+0]=z0; z[g*4+1]=z1; z[g*4+2]=z2; z[g*4+3]=z3;
        pv8[g*4+0]=pv.x; pv8[g*4+1]=pv.y; pv8[g*4+2]=pv.z; pv8[g*4+3]=pv.w;
        S += (z0 + z1) + (z2 + z3);
        mx = fmaxf(mx, fmaxf(fmaxf(z0, z1), fmaxf(z2, z3)));
    }

    S  = block_reduce(S,  rbuf, false);
    mx = block_reduce(mx, rbuf, true);

    float tau;
    if (1.0f + 2047.0f * mx - S > 0.0f) {
        tau = (S + 1.0f) * (1.0f / 2047.0f);
    } else {
        // exact fallback (ascending bitonic sort + scan) — effectively never taken
#pragma unroll
        for (int g = 0; g < 2; g++)
#pragma unroll
            for (int j = 0; j < 4; j++)
                s_a[(tid + g * 256) * 4 + j] = z[g * 4 + j];
        __syncthreads();
        for (int k = 2; k <= NF; k <<= 1)
            for (int j = k >> 1; j > 0; j >>= 1) {
                for (int i = tid; i < NF; i += 256) {
                    int ixj = i ^ j;
                    if (ixj > i) {
                        bool up = ((i & k) == 0);
                        float va = s_a[i], vb = s_a[ixj];
                        if ((va > vb) == up) { s_a[i] = vb; s_a[ixj] = va; }
                    }
                }
                __syncthreads();
            }
        float sv[8];
#pragma unroll
        for (int e = 0; e < 8; e++) sv[e] = s_a[tid + e * 256];
        float* src = s_a; float* dst = s_b;
        for (int off = 1; off < NF; off <<= 1) {
            for (int i = tid; i < NF; i += 256)
                dst[i] = src[i] + ((i >= off) ? src[i - off] : 0.0f);
            __syncthreads();
            float* t = src; src = dst; dst = t;
        }
        float kf = 0.0f;
#pragma unroll
        for (int e = 0; e < 8; e++) {
            int i = tid + e * 256;
            if (1.0f + (float)i * sv[e] - src[i] > 0.0f) kf = fmaxf(kf, (float)i);
        }
        kf = block_reduce(kf, rbuf, true);
        int k = (int)kf;
        tau = (src[k] + 1.0f) / (float)k;
        __syncthreads();
    }

    float* om = out + (size_t)row * NF;
    float* op = out + (size_t)NFTOT + (size_t)row * NF;
#pragma unroll
    for (int g = 0; g < 2; g++) {
        const int q = tid + g * 256;
        float m0 = fmaxf(z[g*4+0] - tau, 0.0f);
        float m1 = fmaxf(z[g*4+1] - tau, 0.0f);
        float m2 = fmaxf(z[g*4+2] - tau, 0.0f);
        float m3 = fmaxf(z[g*4+3] - tau, 0.0f);
        ((float4*)om)[q] = make_float4(m0, m1, m2, m3);
        ((float4*)op)[q] = make_float4(pv8[g*4+0] * (GAMMA - m0),
                                       pv8[g*4+1] * (GAMMA - m1),
                                       pv8[g*4+2] * (GAMMA - m2),
                                       pv8[g*4+3] * (GAMMA - m3));
    }
}

// ================================================================
// launch: a, ps, W, b, bn_w, bn_b -> out = concat(m, new_ps)
// ================================================================
extern "C" void kernel_launch(void* const* d_in, const int* in_sizes, int n_in,
                              void* d_out, int out_size) {
    const float* a    = (const float*)d_in[0];
    const float* ps   = (const float*)d_in[1];
    const float* W    = (const float*)d_in[2];
    const float* bn_w = (const float*)d_in[4];
    const float* bn_b = (const float*)d_in[5];
    float* out = (float*)d_out;

    cudaFuncSetAttribute(gemm_hmma_kernel,
                         cudaFuncAttributeMaxDynamicSharedMemorySize,
                         NSTAGE * STG_BYTES);

    conv_kernel<<<CONV_A_BLOCKS + CONV_W_BLOCKS, 256>>>(a, W);
    gemm_hmma_kernel<<<dim3(NF / 128, NROWS / 128), 128, NSTAGE * STG_BYTES>>>(bn_w, bn_b);
    row_kernel<<<NROWS, 256>>>(ps, out);
}

// round 14
// speedup vs baseline: 1.1998x; 1.1382x over previous
#include <cuda_runtime.h>
#include <cuda_fp16.h>
#include <math_constants.h>
#include <cstdint>

// Problem constants
#define NROWS 16384
#define NA    256
#define NF    2048
#define NFTOT (NROWS * NF)
#define GAMMA 1.5f
#define BN_EPS 1e-5f

#define BKB   64            // K per pipeline stage
#define NKIT  (NA / BKB)    // 4
#define STG_BYTES 32768     // A 16KB + B 16KB
#define NSTAGE 3            // 96KB smem -> 2 CTAs/SM

// ---------------- scratch (allocation-free: __device__ globals) ----------------
__device__ __half g_Xh[NROWS * NF];              // GEMM output (fp16)
__device__ __half g_Ah[(size_t)NROWS * NA];      // fp16(a)
__device__ __half g_Wh[(size_t)NF * NA];         // fp16(W)
__device__ float  g_colsum[NF];
__device__ float  g_colsq[NF];
__device__ float  g_scale[NF];
__device__ float  g_shift[NF];

// ================= PTX helpers (baseline ISA only: valid on sm_103) =================
__device__ __forceinline__ uint32_t smem_u32(const void* p) {
    uint32_t a;
    asm("{ .reg .u64 t; cvta.to.shared.u64 t, %1; cvt.u32.u64 %0, t; }" : "=r"(a) : "l"(p));
    return a;
}
__device__ __forceinline__ void cp16(uint32_t sm, const void* g) {
    asm volatile("cp.async.cg.shared.global [%0], [%1], 16;" :: "r"(sm),
                 "l"(__cvta_generic_to_global(g)));
}
#define CP_COMMIT() asm volatile("cp.async.commit_group;" ::: "memory")
#define CP_WAIT(n)  asm volatile("cp.async.wait_group %0;" :: "n"(n) : "memory")

__device__ __forceinline__ void ldsm_x4(uint32_t& r0, uint32_t& r1, uint32_t& r2,
                                        uint32_t& r3, uint32_t addr) {
    asm volatile("ldmatrix.sync.aligned.m8n8.x4.shared.b16 {%0,%1,%2,%3}, [%4];"
        : "=r"(r0), "=r"(r1), "=r"(r2), "=r"(r3) : "r"(addr));
}
__device__ __forceinline__ void mma16816(float* d, const uint32_t* a,
                                         uint32_t b0, uint32_t b1) {
    asm volatile("mma.sync.aligned.m16n8k16.row.col.f32.f16.f16.f32 "
        "{%0,%1,%2,%3}, {%4,%5,%6,%7}, {%8,%9}, {%0,%1,%2,%3};"
        : "+f"(d[0]), "+f"(d[1]), "+f"(d[2]), "+f"(d[3])
        : "r"(a[0]), "r"(a[1]), "r"(a[2]), "r"(a[3]), "r"(b0), "r"(b1));
}
__device__ __forceinline__ uint32_t h2_bits(__half2 h) {
    union { __half2 h; uint32_t u; } cv;
    cv.h = h;
    return cv.u;
}
__device__ __forceinline__ float2 h2_f2(uint32_t u) {
    union { uint32_t u; __half2 h; } cv; cv.u = u;
    return __half22float2(cv.h);
}

// ================================================================
// K1: merged fp32->fp16 convert of A and W + zero stats.
// 2 float4 per thread (R13-verified: 7.0us).
// (bias b omitted: cancelled exactly by BatchNorm mean subtraction)
// ================================================================
#define CONV_A_BLOCKS (NROWS * NA / 2048)   // 2048
#define CONV_W_BLOCKS (NF * NA / 2048)      // 256
__global__ void __launch_bounds__(256)
conv_kernel(const float* __restrict__ a, const float* __restrict__ W) {
    if (blockIdx.x < CONV_A_BLOCKS) {
        int i4 = blockIdx.x * 512 + threadIdx.x;
#pragma unroll
        for (int r = 0; r < 2; r++) {
            float4 v = ((const float4*)a)[i4 + r * 256];
            uint2 o;
            o.x = h2_bits(__floats2half2_rn(v.x, v.y));
            o.y = h2_bits(__floats2half2_rn(v.z, v.w));
            ((uint2*)g_Ah)[i4 + r * 256] = o;
        }
    } else {
        int b = blockIdx.x - CONV_A_BLOCKS;
        int i4 = b * 512 + threadIdx.x;
#pragma unroll
        for (int r = 0; r < 2; r++) {
            float4 v = ((const float4*)W)[i4 + r * 256];
            uint2 o;
            o.x = h2_bits(__floats2half2_rn(v.x, v.y));
            o.y = h2_bits(__floats2half2_rn(v.z, v.w));
            ((uint2*)g_Wh)[i4 + r * 256] = o;
        }
        if (b < 8) {
            int f = b * 256 + threadIdx.x;
            g_colsum[f] = 0.0f; g_colsq[f] = 0.0f;
        }
    }
}

// ================================================================
// K2: HMMA GEMM fp16->fp32 — exact R11 configuration (measured
// ~62us, at the mma.sync roofline): CTA 128x128, 4 warps (2M x 2N),
// warp tile 64x64, BK=64, 3-stage cp.async ring, lookahead 2.
// NO fused finalize (R13 showed the exit threadfence costs ~20us).
// ================================================================
__global__ void __launch_bounds__(128, 2)
gemm_hmma_kernel() {
    extern __shared__ char smem[];
    const uint32_t sb = smem_u32(smem);
    const int tid = threadIdx.x;
    const int wid = tid >> 5, lid = tid & 31;
    const int warpM = wid & 1, warpN = wid >> 1;
    const int m0 = blockIdx.y * 128;
    const int f0 = blockIdx.x * 128;

    const int s = tid & 7;
    const int r0 = tid >> 3;
    const uint32_t swc = (uint32_t)((s ^ (r0 & 7)) << 4);
    const uint32_t smA = sb + (uint32_t)r0 * 128u + swc;
    const uint32_t smB = smA + 16384u;
    const char* gA = (const char*)(g_Ah + (size_t)(m0 + r0) * NA) + s * 16;
    const char* gB = (const char*)(g_Wh + (size_t)(f0 + r0) * NA) + s * 16;

    uint32_t rbA[4], rbB[4], segoff[4];
#pragma unroll
    for (int t = 0; t < 4; t++) {
        rbA[t] = sb + (uint32_t)(warpM * 64 + t * 16 + (lid & 15)) * 128u;
        rbB[t] = sb + 16384u + (uint32_t)(warpN * 64 + t * 16 + (lid & 15)) * 128u;
    }
#pragma unroll
    for (int ks = 0; ks < 4; ks++)
        segoff[ks] = (uint32_t)(((2 * ks + (lid >> 4)) ^ (lid & 7)) << 4);

    float acc[4][8][4];
#pragma unroll
    for (int t = 0; t < 4; t++)
#pragma unroll
        for (int j = 0; j < 8; j++)
#pragma unroll
            for (int e = 0; e < 4; e++) acc[t][j][e] = 0.0f;

#pragma unroll
    for (int p = 0; p < 2; p++) {
        const uint32_t so = p * STG_BYTES;
        const int go = p * 128;
#pragma unroll
        for (int j = 0; j < 8; j++) {
            cp16(smA + so + j * 2048u, gA + (size_t)j * 16 * (NA * 2) + go);
            cp16(smB + so + j * 2048u, gB + (size_t)j * 16 * (NA * 2) + go);
        }
        CP_COMMIT();
    }

#pragma unroll
    for (int it = 0; it < NKIT; it++) {
        CP_WAIT(1);
        __syncthreads();
        if (it + 2 < NKIT) {
            const uint32_t so = ((it + 2) % 3) * STG_BYTES;
            const int go = (it + 2) * 128;
#pragma unroll
            for (int j = 0; j < 8; j++) {
                cp16(smA + so + j * 2048u, gA + (size_t)j * 16 * (NA * 2) + go);
                cp16(smB + so + j * 2048u, gB + (size_t)j * 16 * (NA * 2) + go);
            }
        }
        CP_COMMIT();

        const uint32_t so = (it % 3) * STG_BYTES;
#pragma unroll
        for (int ks = 0; ks < 4; ks++) {
            uint32_t af[4][4], bf[4][4];
#pragma unroll
            for (int t = 0; t < 4; t++)
                ldsm_x4(af[t][0], af[t][1], af[t][2], af[t][3],
                        rbA[t] + so + segoff[ks]);
#pragma unroll
            for (int u = 0; u < 4; u++)
                ldsm_x4(bf[u][0], bf[u][1], bf[u][2], bf[u][3],
                        rbB[u] + so + segoff[ks]);
#pragma unroll
            for (int t = 0; t < 4; t++)
#pragma unroll
                for (int u = 0; u < 4; u++) {
                    mma16816(acc[t][2 * u],     af[t], bf[u][0], bf[u][2]);
                    mma16816(acc[t][2 * u + 1], af[t], bf[u][1], bf[u][3]);
                }
        }
    }

    // epilogue: C -> g_Xh (half2 stores) + fused column stats (fp32)
#pragma unroll
    for (int t = 0; t < 4; t++) {
        const int rbase = m0 + warpM * 64 + t * 16 + (lid >> 2);
#pragma unroll
        for (int j = 0; j < 8; j++) {
            const int col = f0 + warpN * 64 + j * 8 + (lid & 3) * 2;
            *(__half2*)&g_Xh[(size_t)rbase * NF + col] =
                __floats2half2_rn(acc[t][j][0], acc[t][j][1]);
            *(__half2*)&g_Xh[(size_t)(rbase + 8) * NF + col] =
                __floats2half2_rn(acc[t][j][2], acc[t][j][3]);
        }
    }
    const unsigned FULL = 0xffffffffu;
#pragma unroll
    for (int j = 0; j < 8; j++) {
        float s0 = 0, s1 = 0, q0 = 0, q1 = 0;
#pragma unroll
        for (int t = 0; t < 4; t++) {
            s0 += acc[t][j][0] + acc[t][j][2];
            s1 += acc[t][j][1] + acc[t][j][3];
            q0 += acc[t][j][0]*acc[t][j][0] + acc[t][j][2]*acc[t][j][2];
            q1 += acc[t][j][1]*acc[t][j][1] + acc[t][j][3]*acc[t][j][3];
        }
#pragma unroll
        for (int o = 16; o >= 4; o >>= 1) {
            s0 += __shfl_down_sync(FULL, s0, o);
            s1 += __shfl_down_sync(FULL, s1, o);
            q0 += __shfl_down_sync(FULL, q0, o);
            q1 += __shfl_down_sync(FULL, q1, o);
        }
        if (lid < 4) {
            const int col = f0 + warpN * 64 + j * 8 + lid * 2;
            atomicAdd(&g_colsum[col], s0);
            atomicAdd(&g_colsum[col + 1], s1);
            atomicAdd(&g_colsq[col], q0);
            atomicAdd(&g_colsq[col + 1], q1);
        }
    }
}

// ================================================================
// K3: finalize column stats -> scale/shift (separate tiny kernel —
// measured cheaper than a fenced last-CTA fuse)
// ================================================================
__global__ void __launch_bounds__(256)
finalize_kernel(const float* __restrict__ bn_w, const float* __restrict__ bn_b) {
    const int f = blockIdx.x * 256 + threadIdx.x;
    const float inv_n = 1.0f / (float)NROWS;
    float mean = g_colsum[f] * inv_n;
    float var  = fmaxf(g_colsq[f] * inv_n - mean * mean, 0.0f);
    float rstd = rsqrtf(var + BN_EPS);
    float sc = bn_w[f] * rstd;
    g_scale[f] = sc;
    g_shift[f] = bn_b[f] - mean * sc;
}

// ================================================================
// K4: per-row sparsemax + outputs (coalesced; lean — R11-verified 67.9us)
// ================================================================
__device__ __forceinline__ float block_reduce(float v, float* buf, bool do_max) {
    const unsigned FULL = 0xffffffffu;
#pragma unroll
    for (int o = 16; o > 0; o >>= 1) {
        float t = __shfl_down_sync(FULL, v, o);
        v = do_max ? fmaxf(v, t) : (v + t);
    }
    const int w = threadIdx.x >> 5, l = threadIdx.x & 31;
    if (l == 0) buf[w] = v;
    __syncthreads();
    if (threadIdx.x < 8) {
        v = buf[threadIdx.x];
#pragma unroll
        for (int o = 4; o > 0; o >>= 1) {
            float t = __shfl_down_sync(0xffu, v, o);
            v = do_max ? fmaxf(v, t) : (v + t);
        }
        if (threadIdx.x == 0) buf[0] = v;
    }
    __syncthreads();
    float r = buf[0];
    __syncthreads();
    return r;
}

__global__ void __launch_bounds__(256)
row_kernel(const float* __restrict__ ps, float* __restrict__ out) {
    __shared__ float s_a[NF];
    __shared__ float s_b[NF];
    __shared__ float rbuf[8];

    const int row = blockIdx.x;
    const int tid = threadIdx.x;

    const uint2*  xp  = (const uint2*)(g_Xh + (size_t)row * NF);
    const float4* pp  = (const float4*)(ps  + (size_t)row * NF);
    const float4* scp = (const float4*)g_scale;
    const float4* shp = (const float4*)g_shift;

    float z[8], pv8[8];
    float S = 0.0f, mx = -CUDART_INF_F;

#pragma unroll
    for (int g = 0; g < 2; g++) {
        const int q = tid + g * 256;
        uint2  xv = xp[q];
        float4 pv = pp[q];
        float4 sc = scp[q], sh = shp[q];

        float2 x01 = h2_f2(xv.x);
        float2 x23 = h2_f2(xv.y);

        float z0 = fmaf(x01.x, sc.x, sh.x) * pv.x;
        float z1 = fmaf(x01.y, sc.y, sh.y) * pv.y;
        float z2 = fmaf(x23.x, sc.z, sh.z) * pv.z;
        float z3 = fmaf(x23.y, sc.w, sh.w) * pv.w;
        z[g*4+0]=z0; z[g*4+1]=z1; z[g*4+2]=z2; z[g*4+3]=z3;
        pv8[g*4+0]=pv.x; pv8[g*4+1]=pv.y; pv8[g*4+2]=pv.z; pv8[g*4+3]=pv.w;
        S += (z0 + z1) + (z2 + z3);
        mx = fmaxf(mx, fmaxf(fmaxf(z0, z1), fmaxf(z2, z3)));
    }

    S  = block_reduce(S,  rbuf, false);
    mx = block_reduce(mx, rbuf, true);

    float tau;
    if (1.0f + 2047.0f * mx - S > 0.0f) {
        tau = (S + 1.0f) * (1.0f / 2047.0f);
    } else {
        // exact fallback (ascending bitonic sort + scan) — effectively never taken
#pragma unroll
        for (int g = 0; g < 2; g++)
#pragma unroll
            for (int j = 0; j < 4; j++)
                s_a[(tid + g * 256) * 4 + j] = z[g * 4 + j];
        __syncthreads();
        for (int k = 2; k <= NF; k <<= 1)
            for (int j = k >> 1; j > 0; j >>= 1) {
                for (int i = tid; i < NF; i += 256) {
                    int ixj = i ^ j;
                    if (ixj > i) {
                        bool up = ((i & k) == 0);
                        float va = s_a[i], vb = s_a[ixj];
                        if ((va > vb) == up) { s_a[i] = vb; s_a[ixj] = va; }
                    }
                }
                __syncthreads();
            }
        float sv[8];
#pragma unroll
        for (int e = 0; e < 8; e++) sv[e] = s_a[tid + e * 256];
        float* src = s_a; float* dst = s_b;
        for (int off = 1; off < NF; off <<= 1) {
            for (int i = tid; i < NF; i += 256)
                dst[i] = src[i] + ((i >= off) ? src[i - off] : 0.0f);
            __syncthreads();
            float* t = src; src = dst; dst = t;
        }
        float kf = 0.0f;
#pragma unroll
        for (int e = 0; e < 8; e++) {
            int i = tid + e * 256;
            if (1.0f + (float)i * sv[e] - src[i] > 0.0f) kf = fmaxf(kf, (float)i);
        }
        kf = block_reduce(kf, rbuf, true);
        int k = (int)kf;
        tau = (src[k] + 1.0f) / (float)k;
        __syncthreads();
    }

    float* om = out + (size_t)row * NF;
    float* op = out + (size_t)NFTOT + (size_t)row * NF;
#pragma unroll
    for (int g = 0; g < 2; g++) {
        const int q = tid + g * 256;
        float m0 = fmaxf(z[g*4+0] - tau, 0.0f);
        float m1 = fmaxf(z[g*4+1] - tau, 0.0f);
        float m2 = fmaxf(z[g*4+2] - tau, 0.0f);
        float m3 = fmaxf(z[g*4+3] - tau, 0.0f);
        ((float4*)om)[q] = make_float4(m0, m1, m2, m3);
        ((float4*)op)[q] = make_float4(pv8[g*4+0] * (GAMMA - m0),
                                       pv8[g*4+1] * (GAMMA - m1),
                                       pv8[g*4+2] * (GAMMA - m2),
                                       pv8[g*4+3] * (GAMMA - m3));
    }
}

// ================================================================
// launch: a, ps, W, b, bn_w, bn_b -> out = concat(m, new_ps)
// ================================================================
extern "C" void kernel_launch(void* const* d_in, const int* in_sizes, int n_in,
                              void* d_out, int out_size) {
    const float* a    = (const float*)d_in[0];
    const float* ps   = (const float*)d_in[1];
    const float* W    = (const float*)d_in[2];
    const float* bn_w = (const float*)d_in[4];
    const float* bn_b = (const float*)d_in[5];
    float* out = (float*)d_out;

    cudaFuncSetAttribute(gemm_hmma_kernel,
                         cudaFuncAttributeMaxDynamicSharedMemorySize,
                         NSTAGE * STG_BYTES);

    conv_kernel<<<CONV_A_BLOCKS + CONV_W_BLOCKS, 256>>>(a, W);
    gemm_hmma_kernel<<<dim3(NF / 128, NROWS / 128), 128, NSTAGE * STG_BYTES>>>();
    finalize_kernel<<<NF / 256, 256>>>(bn_w, bn_b);
    row_kernel<<<NROWS, 256>>>(ps, out);
}

// round 15
// speedup vs baseline: 1.2733x; 1.0613x over previous
#include <cuda_runtime.h>
#include <cuda_fp16.h>
#include <math_constants.h>
#include <cstdint>

// Problem constants
#define NROWS 16384
#define NA    256
#define NF    2048
#define NFTOT (NROWS * NF)
#define GAMMA 1.5f
#define BN_EPS 1e-5f

#define BKB   64            // K per pipeline stage
#define NKIT  (NA / BKB)    // 4
#define STG_BYTES 32768     // A 16KB + B 16KB
#define NSTAGE 3            // 96KB smem -> 2 CTAs/SM

// ---------------- scratch (allocation-free: __device__ globals) ----------------
__device__ __half g_Xh[NROWS * NF];              // GEMM output (fp16)
__device__ __half g_Ah[(size_t)NROWS * NA];      // fp16(a)
__device__ __half g_Wh[(size_t)NF * NA];         // fp16(W)
__device__ float  g_colsum[NF];
__device__ float  g_colsq[NF];
__device__ float  g_scale[NF];
__device__ float  g_shift[NF];

// ================= PTX helpers (baseline ISA only: valid on sm_103) =================
__device__ __forceinline__ uint32_t smem_u32(const void* p) {
    uint32_t a;
    asm("{ .reg .u64 t; cvta.to.shared.u64 t, %1; cvt.u32.u64 %0, t; }" : "=r"(a) : "l"(p));
    return a;
}
__device__ __forceinline__ void cp16(uint32_t sm, const void* g) {
    asm volatile("cp.async.cg.shared.global [%0], [%1], 16;" :: "r"(sm),
                 "l"(__cvta_generic_to_global(g)));
}
#define CP_COMMIT() asm volatile("cp.async.commit_group;" ::: "memory")
#define CP_WAIT(n)  asm volatile("cp.async.wait_group %0;" :: "n"(n) : "memory")

__device__ __forceinline__ void ldsm_x4(uint32_t& r0, uint32_t& r1, uint32_t& r2,
                                        uint32_t& r3, uint32_t addr) {
    asm volatile("ldmatrix.sync.aligned.m8n8.x4.shared.b16 {%0,%1,%2,%3}, [%4];"
        : "=r"(r0), "=r"(r1), "=r"(r2), "=r"(r3) : "r"(addr));
}
__device__ __forceinline__ void mma16816(float* d, const uint32_t* a,
                                         uint32_t b0, uint32_t b1) {
    asm volatile("mma.sync.aligned.m16n8k16.row.col.f32.f16.f16.f32 "
        "{%0,%1,%2,%3}, {%4,%5,%6,%7}, {%8,%9}, {%0,%1,%2,%3};"
        : "+f"(d[0]), "+f"(d[1]), "+f"(d[2]), "+f"(d[3])
        : "r"(a[0]), "r"(a[1]), "r"(a[2]), "r"(a[3]), "r"(b0), "r"(b1));
}
__device__ __forceinline__ uint32_t h2_bits(__half2 h) {
    union { __half2 h; uint32_t u; } cv;
    cv.h = h;
    return cv.u;
}
__device__ __forceinline__ float2 h2_f2(uint32_t u) {
    union { uint32_t u; __half2 h; } cv; cv.u = u;
    return __half22float2(cv.h);
}

// ================================================================
// K1: merged fp32->fp16 convert of A and W + zero stats.
// 2 float4 per thread (R13-verified: 7.0us).
// (bias b omitted: cancelled exactly by BatchNorm mean subtraction)
// ================================================================
#define CONV_A_BLOCKS (NROWS * NA / 2048)   // 2048
#define CONV_W_BLOCKS (NF * NA / 2048)      // 256
__global__ void __launch_bounds__(256)
conv_kernel(const float* __restrict__ a, const float* __restrict__ W) {
    if (blockIdx.x < CONV_A_BLOCKS) {
        int i4 = blockIdx.x * 512 + threadIdx.x;
#pragma unroll
        for (int r = 0; r < 2; r++) {
            float4 v = __ldcs(((const float4*)a) + i4 + r * 256);
            uint2 o;
            o.x = h2_bits(__floats2half2_rn(v.x, v.y));
            o.y = h2_bits(__floats2half2_rn(v.z, v.w));
            ((uint2*)g_Ah)[i4 + r * 256] = o;
        }
    } else {
        int b = blockIdx.x - CONV_A_BLOCKS;
        int i4 = b * 512 + threadIdx.x;
#pragma unroll
        for (int r = 0; r < 2; r++) {
            float4 v = __ldcs(((const float4*)W) + i4 + r * 256);
            uint2 o;
            o.x = h2_bits(__floats2half2_rn(v.x, v.y));
            o.y = h2_bits(__floats2half2_rn(v.z, v.w));
            ((uint2*)g_Wh)[i4 + r * 256] = o;
        }
        if (b < 8) {
            int f = b * 256 + threadIdx.x;
            g_colsum[f] = 0.0f; g_colsq[f] = 0.0f;
        }
    }
}

// ================================================================
// K2: HMMA GEMM fp16->fp32 — R11 configuration (measured ~62us, at
// the mma.sync roofline): CTA 128x128, 4 warps (2M x 2N), warp tile
// 64x64, BK=64, 3-stage cp.async ring, lookahead 2.
// ================================================================
__global__ void __launch_bounds__(128, 2)
gemm_hmma_kernel() {
    extern __shared__ char smem[];
    const uint32_t sb = smem_u32(smem);
    const int tid = threadIdx.x;
    const int wid = tid >> 5, lid = tid & 31;
    const int warpM = wid & 1, warpN = wid >> 1;
    const int m0 = blockIdx.y * 128;
    const int f0 = blockIdx.x * 128;

    const int s = tid & 7;
    const int r0 = tid >> 3;
    const uint32_t swc = (uint32_t)((s ^ (r0 & 7)) << 4);
    const uint32_t smA = sb + (uint32_t)r0 * 128u + swc;
    const uint32_t smB = smA + 16384u;
    const char* gA = (const char*)(g_Ah + (size_t)(m0 + r0) * NA) + s * 16;
    const char* gB = (const char*)(g_Wh + (size_t)(f0 + r0) * NA) + s * 16;

    uint32_t rbA[4], rbB[4], segoff[4];
#pragma unroll
    for (int t = 0; t < 4; t++) {
        rbA[t] = sb + (uint32_t)(warpM * 64 + t * 16 + (lid & 15)) * 128u;
        rbB[t] = sb + 16384u + (uint32_t)(warpN * 64 + t * 16 + (lid & 15)) * 128u;
    }
#pragma unroll
    for (int ks = 0; ks < 4; ks++)
        segoff[ks] = (uint32_t)(((2 * ks + (lid >> 4)) ^ (lid & 7)) << 4);

    float acc[4][8][4];
#pragma unroll
    for (int t = 0; t < 4; t++)
#pragma unroll
        for (int j = 0; j < 8; j++)
#pragma unroll
            for (int e = 0; e < 4; e++) acc[t][j][e] = 0.0f;

#pragma unroll
    for (int p = 0; p < 2; p++) {
        const uint32_t so = p * STG_BYTES;
        const int go = p * 128;
#pragma unroll
        for (int j = 0; j < 8; j++) {
            cp16(smA + so + j * 2048u, gA + (size_t)j * 16 * (NA * 2) + go);
            cp16(smB + so + j * 2048u, gB + (size_t)j * 16 * (NA * 2) + go);
        }
        CP_COMMIT();
    }

#pragma unroll
    for (int it = 0; it < NKIT; it++) {
        CP_WAIT(1);
        __syncthreads();
        if (it + 2 < NKIT) {
            const uint32_t so = ((it + 2) % 3) * STG_BYTES;
            const int go = (it + 2) * 128;
#pragma unroll
            for (int j = 0; j < 8; j++) {
                cp16(smA + so + j * 2048u, gA + (size_t)j * 16 * (NA * 2) + go);
                cp16(smB + so + j * 2048u, gB + (size_t)j * 16 * (NA * 2) + go);
            }
        }
        CP_COMMIT();

        const uint32_t so = (it % 3) * STG_BYTES;
#pragma unroll
        for (int ks = 0; ks < 4; ks++) {
            uint32_t af[4][4], bf[4][4];
#pragma unroll
            for (int t = 0; t < 4; t++)
                ldsm_x4(af[t][0], af[t][1], af[t][2], af[t][3],
                        rbA[t] + so + segoff[ks]);
#pragma unroll
            for (int u = 0; u < 4; u++)
                ldsm_x4(bf[u][0], bf[u][1], bf[u][2], bf[u][3],
                        rbB[u] + so + segoff[ks]);
#pragma unroll
            for (int t = 0; t < 4; t++)
#pragma unroll
                for (int u = 0; u < 4; u++) {
                    mma16816(acc[t][2 * u],     af[t], bf[u][0], bf[u][2]);
                    mma16816(acc[t][2 * u + 1], af[t], bf[u][1], bf[u][3]);
                }
        }
    }

    // epilogue: C -> g_Xh (half2 stores) + fused column stats (fp32)
#pragma unroll
    for (int t = 0; t < 4; t++) {
        const int rbase = m0 + warpM * 64 + t * 16 + (lid >> 2);
#pragma unroll
        for (int j = 0; j < 8; j++) {
            const int col = f0 + warpN * 64 + j * 8 + (lid & 3) * 2;
            *(__half2*)&g_Xh[(size_t)rbase * NF + col] =
                __floats2half2_rn(acc[t][j][0], acc[t][j][1]);
            *(__half2*)&g_Xh[(size_t)(rbase + 8) * NF + col] =
                __floats2half2_rn(acc[t][j][2], acc[t][j][3]);
        }
    }
    const unsigned FULL = 0xffffffffu;
#pragma unroll
    for (int j = 0; j < 8; j++) {
        float s0 = 0, s1 = 0, q0 = 0, q1 = 0;
#pragma unroll
        for (int t = 0; t < 4; t++) {
            s0 += acc[t][j][0] + acc[t][j][2];
            s1 += acc[t][j][1] + acc[t][j][3];
            q0 += acc[t][j][0]*acc[t][j][0] + acc[t][j][2]*acc[t][j][2];
            q1 += acc[t][j][1]*acc[t][j][1] + acc[t][j][3]*acc[t][j][3];
        }
#pragma unroll
        for (int o = 16; o >= 4; o >>= 1) {
            s0 += __shfl_down_sync(FULL, s0, o);
            s1 += __shfl_down_sync(FULL, s1, o);
            q0 += __shfl_down_sync(FULL, q0, o);
            q1 += __shfl_down_sync(FULL, q1, o);
        }
        if (lid < 4) {
            const int col = f0 + warpN * 64 + j * 8 + lid * 2;
            atomicAdd(&g_colsum[col], s0);
            atomicAdd(&g_colsum[col + 1], s1);
            atomicAdd(&g_colsq[col], q0);
            atomicAdd(&g_colsq[col + 1], q1);
        }
    }
}

// ================================================================
// K3: finalize column stats -> scale/shift (separate tiny kernel)
// ================================================================
__global__ void __launch_bounds__(256)
finalize_kernel(const float* __restrict__ bn_w, const float* __restrict__ bn_b) {
    const int f = blockIdx.x * 256 + threadIdx.x;
    const float inv_n = 1.0f / (float)NROWS;
    float mean = g_colsum[f] * inv_n;
    float var  = fmaxf(g_colsq[f] * inv_n - mean * mean, 0.0f);
    float rstd = rsqrtf(var + BN_EPS);
    float sc = bn_w[f] * rstd;
    g_scale[f] = sc;
    g_shift[f] = bn_b[f] - mean * sc;
}

// ================================================================
// K4: per-row sparsemax + outputs. Streaming cache hints on the
// touch-once streams (x, ps loads; out stores); scale/shift stay
// default-cached (broadcast-reused across all blocks).
// ================================================================
__device__ __forceinline__ float block_reduce(float v, float* buf, bool do_max) {
    const unsigned FULL = 0xffffffffu;
#pragma unroll
    for (int o = 16; o > 0; o >>= 1) {
        float t = __shfl_down_sync(FULL, v, o);
        v = do_max ? fmaxf(v, t) : (v + t);
    }
    const int w = threadIdx.x >> 5, l = threadIdx.x & 31;
    if (l == 0) buf[w] = v;
    __syncthreads();
    if (threadIdx.x < 8) {
        v = buf[threadIdx.x];
#pragma unroll
        for (int o = 4; o > 0; o >>= 1) {
            float t = __shfl_down_sync(0xffu, v, o);
            v = do_max ? fmaxf(v, t) : (v + t);
        }
        if (threadIdx.x == 0) buf[0] = v;
    }
    __syncthreads();
    float r = buf[0];
    __syncthreads();
    return r;
}

__global__ void __launch_bounds__(256)
row_kernel(const float* __restrict__ ps, float* __restrict__ out) {
    __shared__ float s_a[NF];
    __shared__ float s_b[NF];
    __shared__ float rbuf[8];

    const int row = blockIdx.x;
    const int tid = threadIdx.x;

    const uint2*  xp  = (const uint2*)(g_Xh + (size_t)row * NF);
    const float4* pp  = (const float4*)(ps  + (size_t)row * NF);
    const float4* scp = (const float4*)g_scale;
    const float4* shp = (const float4*)g_shift;

    float z[8], pv8[8];
    float S = 0.0f, mx = -CUDART_INF_F;

#pragma unroll
    for (int g = 0; g < 2; g++) {
        const int q = tid + g * 256;
        uint2  xv = __ldcs(xp + q);        // streaming: touch-once
        float4 pv = __ldcs(pp + q);        // streaming: touch-once
        float4 sc = scp[q], sh = shp[q];   // cached: reused by all blocks

        float2 x01 = h2_f2(xv.x);
        float2 x23 = h2_f2(xv.y);

        float z0 = fmaf(x01.x, sc.x, sh.x) * pv.x;
        float z1 = fmaf(x01.y, sc.y, sh.y) * pv.y;
        float z2 = fmaf(x23.x, sc.z, sh.z) * pv.z;
        float z3 = fmaf(x23.y, sc.w, sh.w) * pv.w;
        z[g*4+0]=z0; z[g*4+1]=z1; z[g*4+2]=z2; z[g*4+3]=z3;
        pv8[g*4+0]=pv.x; pv8[g*4+1]=pv.y; pv8[g*4+2]=pv.z; pv8[g*4+3]=pv.w;
        S += (z0 + z1) + (z2 + z3);
        mx = fmaxf(mx, fmaxf(fmaxf(z0, z1), fmaxf(z2, z3)));
    }

    S  = block_reduce(S,  rbuf, false);
    mx = block_reduce(mx, rbuf, true);

    float tau;
    if (1.0f + 2047.0f * mx - S > 0.0f) {
        tau = (S + 1.0f) * (1.0f / 2047.0f);
    } else {
        // exact fallback (ascending bitonic sort + scan) — effectively never taken
#pragma unroll
        for (int g = 0; g < 2; g++)
#pragma unroll
            for (int j = 0; j < 4; j++)
                s_a[(tid + g * 256) * 4 + j] = z[g * 4 + j];
        __syncthreads();
        for (int k = 2; k <= NF; k <<= 1)
            for (int j = k >> 1; j > 0; j >>= 1) {
                for (int i = tid; i < NF; i += 256) {
                    int ixj = i ^ j;
                    if (ixj > i) {
                        bool up = ((i & k) == 0);
                        float va = s_a[i], vb = s_a[ixj];
                        if ((va > vb) == up) { s_a[i] = vb; s_a[ixj] = va; }
                    }
                }
                __syncthreads();
            }
        float sv[8];
#pragma unroll
        for (int e = 0; e < 8; e++) sv[e] = s_a[tid + e * 256];
        float* src = s_a; float* dst = s_b;
        for (int off = 1; off < NF; off <<= 1) {
            for (int i = tid; i < NF; i += 256)
                dst[i] = src[i] + ((i >= off) ? src[i - off] : 0.0f);
            __syncthreads();
            float* t = src; src = dst; dst = t;
        }
        float kf = 0.0f;
#pragma unroll
        for (int e = 0; e < 8; e++) {
            int i = tid + e * 256;
            if (1.0f + (float)i * sv[e] - src[i] > 0.0f) kf = fmaxf(kf, (float)i);
        }
        kf = block_reduce(kf, rbuf, true);
        int k = (int)kf;
        tau = (src[k] + 1.0f) / (float)k;
        __syncthreads();
    }

    float4* om = (float4*)(out + (size_t)row * NF);
    float4* op = (float4*)(out + (size_t)NFTOT + (size_t)row * NF);
#pragma unroll
    for (int g = 0; g < 2; g++) {
        const int q = tid + g * 256;
        float m0 = fmaxf(z[g*4+0] - tau, 0.0f);
        float m1 = fmaxf(z[g*4+1] - tau, 0.0f);
        float m2 = fmaxf(z[g*4+2] - tau, 0.0f);
        float m3 = fmaxf(z[g*4+3] - tau, 0.0f);
        __stcs(om + q, make_float4(m0, m1, m2, m3));                 // streaming store
        __stcs(op + q, make_float4(pv8[g*4+0] * (GAMMA - m0),        // streaming store
                                   pv8[g*4+1] * (GAMMA - m1),
                                   pv8[g*4+2] * (GAMMA - m2),
                                   pv8[g*4+3] * (GAMMA - m3)));
    }
}

// ================================================================
// launch: a, ps, W, b, bn_w, bn_b -> out = concat(m, new_ps)
// ================================================================
extern "C" void kernel_launch(void* const* d_in, const int* in_sizes, int n_in,
                              void* d_out, int out_size) {
    const float* a    = (const float*)d_in[0];
    const float* ps   = (const float*)d_in[1];
    const float* W    = (const float*)d_in[2];
    const float* bn_w = (const float*)d_in[4];
    const float* bn_b = (const float*)d_in[5];
    float* out = (float*)d_out;

    cudaFuncSetAttribute(gemm_hmma_kernel,
                         cudaFuncAttributeMaxDynamicSharedMemorySize,
                         NSTAGE * STG_BYTES);

    conv_kernel<<<CONV_A_BLOCKS + CONV_W_BLOCKS, 256>>>(a, W);
    gemm_hmma_kernel<<<dim3(NF / 128, NROWS / 128), 128, NSTAGE * STG_BYTES>>>();
    finalize_kernel<<<NF / 256, 256>>>(bn_w, bn_b);
    row_kernel<<<NROWS, 256>>>(ps, out);
}